// round 17
// baseline (speedup 1.0000x reference)
#include <cuda_runtime.h>
#include <cuda_fp16.h>
#include <stdint.h>

#define Bdim 4
#define Ndim 512
#define NCdim 128
#define ECdim 32
#define OCdim 64
#define KNdim 10
#define KEdim 5
#define NIN 192   // 2*EC + NC
#define EWARPS 8
#define PX 12     // node-kernel transposed pitch

// packed per-node vectors: {n1, n2, q1, q2} per channel (float4-interleaved)
__device__ float g_pk[Bdim*Ndim*OCdim*4];
// x_in (0..31) ++ x_out (32..63) per node
__device__ float g_x[Bdim*Ndim*64];

__device__ __forceinline__ float silu_f(float x) {
    return __fdividef(x, 1.0f + __expf(-x));
}
// fast silu: x * sigmoid(x) = 0.5x(1 + tanh(x/2)); 1 MUFU
__device__ __forceinline__ float silu_t(float x) {
    float th;
    asm("tanh.approx.f32 %0, %1;" : "=f"(th) : "f"(x * 0.5f));
    return fmaf(0.5f*x, th, 0.5f*x);
}
// packed half2 silu: one MUFU for two channels
__device__ __forceinline__ __half2 silu_h2(float x, float y) {
    __half2 hh = __float22half2_rn(make_float2(0.5f*x, 0.5f*y));
    uint32_t th;
    asm("tanh.approx.f16x2 %0, %1;" : "=r"(th) : "r"(*(uint32_t*)&hh));
    __half2 one = __float2half2_rn(1.f);
    return __hmul2(__hadd2(*(__half2*)&th, one), hh);
}

__device__ __forceinline__ void mma16816(float& c0, float& c1, float& c2, float& c3,
                                         uint32_t a0, uint32_t a1, uint32_t a2, uint32_t a3,
                                         uint32_t b0, uint32_t b1) {
    asm volatile("mma.sync.aligned.m16n8k16.row.col.f32.f16.f16.f32 "
                 "{%0,%1,%2,%3},{%4,%5,%6,%7},{%8,%9},{%0,%1,%2,%3};\n"
                 : "+f"(c0), "+f"(c1), "+f"(c2), "+f"(c3)
                 : "r"(a0), "r"(a1), "r"(a2), "r"(a3), "r"(b0), "r"(b1));
}

__device__ __forceinline__ void split_h2(float x, float y, uint32_t& hi, uint32_t& lo) {
    __half2 h = __float22half2_rn(make_float2(x, y));
    float2 hf = __half22float2(h);
    __half2 l = __float22half2_rn(make_float2(x - hf.x, y - hf.y));
    hi = *(uint32_t*)&h;  lo = *(uint32_t*)&l;
}
__device__ __forceinline__ uint32_t pack_h2(float x, float y) {
    __half2 h = __float22half2_rn(make_float2(x, y));
    return *(uint32_t*)&h;
}

// ---------------------------------------------------------------------------
// Kernel A: masked-mean reduction (round-15/16 winner, unchanged).
// ---------------------------------------------------------------------------
__global__ __launch_bounds__(256)
void reduce_kernel(const float* __restrict__ edge,
                   const int* __restrict__ block_id,
                   const int* __restrict__ vmask)
{
    const int bi = blockIdx.x;
    const int b  = bi / Ndim;
    const int i  = bi % Ndim;
    const int tid = threadIdx.x;

    __shared__ int    s_bid[Ndim];
    __shared__ unsigned char s_vm[Ndim];
    __shared__ float2 s_mask[Ndim];
    __shared__ float  s_red[8][64];
    __shared__ float  s_cnt[2][8];

    for (int k = tid; k < Ndim; k += 256) {
        s_bid[k] = block_id[b*Ndim + k];
        s_vm[k]  = (vmask[b*Ndim + k] != 0) ? 1 : 0;
    }
    __syncthreads();

    const int  bii  = s_bid[i];
    const bool nm_i = (bii >= 0);
    const bool vm_i = (s_vm[i] != 0);

    for (int j = tid; j < Ndim; j += 256) {
        int  bj   = s_bid[j];
        bool nm_j = (bj >= 0);
        bool pv   = nm_i && nm_j;
        bool cij  = pv && ((bii > bj) || (bii == bj && !vm_i));
        bool cji  = pv && ((bj > bii) || (bj == bii && (s_vm[j] == 0)));
        s_mask[j] = make_float2(cij ? 1.f : 0.f, cji ? 1.f : 0.f);
    }
    __syncthreads();

    const int c  = tid & 31;
    const int jl = tid >> 5;

    float acc_in0 = 0.f, acc_in1 = 0.f, acc_out0 = 0.f, acc_out1 = 0.f;
    float cnt_in = 0.f, cnt_out = 0.f;
    const float* erow = edge + ((size_t)(b*Ndim + i) * Ndim) * ECdim + c;
    const float* ecol = edge + ((size_t)b*Ndim) * Ndim * ECdim + (size_t)i*ECdim + c;

    for (int j0 = jl*16; j0 < Ndim; j0 += 128) {
        const float* er = erow + (size_t)j0*ECdim;
        const float* ec = ecol + (size_t)j0*Ndim*ECdim;
        float vin[16], vout[16];
        #pragma unroll
        for (int u = 0; u < 16; u++) {
            vin[u]  = er[(size_t)u*ECdim];
            vout[u] = ec[(size_t)u*Ndim*ECdim];
        }
        #pragma unroll
        for (int u = 0; u < 16; u += 2) {
            float2 m0 = s_mask[j0+u], m1 = s_mask[j0+u+1];
            acc_in0  = fmaf(vin[u],    m0.x, acc_in0);
            acc_in1  = fmaf(vin[u+1],  m1.x, acc_in1);
            acc_out0 = fmaf(vout[u],   m0.y, acc_out0);
            acc_out1 = fmaf(vout[u+1], m1.y, acc_out1);
            cnt_in  += m0.x + m1.x;
            cnt_out += m0.y + m1.y;
        }
    }
    s_red[jl][c]      = acc_in0 + acc_in1;
    s_red[jl][c + 32] = acc_out0 + acc_out1;
    if (c == 0) { s_cnt[0][jl] = cnt_in; s_cnt[1][jl] = cnt_out; }
    __syncthreads();

    if (tid < 64) {
        float s = 0.f, cnt = 0.f;
        #pragma unroll
        for (int r2 = 0; r2 < 8; r2++) { s += s_red[r2][tid]; cnt += s_cnt[tid >> 5][r2]; }
        g_x[(size_t)(b*Ndim + i)*64 + tid] = s / fmaxf(cnt, 1.f);
    }
}

// ---------------------------------------------------------------------------
// Kernel B: batched node GEMVs (unchanged winner).
// ---------------------------------------------------------------------------
__global__ __launch_bounds__(256)
void node_kernel(const float* __restrict__ node,
                 const int* __restrict__ block_id,
                 const float* __restrict__ W_nt, const float* __restrict__ b_nt,
                 const float* __restrict__ W_n1, const float* __restrict__ b_n1,
                 const float* __restrict__ W_f1,
                 const float* __restrict__ W_no1, const float* __restrict__ b_no1,
                 const float* __restrict__ g_no, const float* __restrict__ be_no,
                 const float* __restrict__ W_no2, const float* __restrict__ b_no2,
                 float* __restrict__ out_node)
{
    const int b  = blockIdx.x >> 6;
    const int i0 = (blockIdx.x & 63) * 8;
    const int tid = threadIdx.x;
    const int w    = tid >> 5;
    const int lane = tid & 31;

    __shared__ int s_bid8[8];
    __shared__ float s_x[NIN*PX];
    __shared__ float s_hT[NCdim*PX];
    __shared__ float s_nT[NCdim*PX];
    __shared__ float s_tT[NCdim*PX];
    __shared__ float s_vT[NCdim*PX];

    if (tid < 8) s_bid8[tid] = block_id[b*Ndim + i0 + tid];
    __syncthreads();

    {
        const int i = i0 + w;
        const bool nm_i = (s_bid8[w] >= 0);
        const size_t xo = (size_t)(b*Ndim + i)*64;
        s_x[lane*PX + w]      = g_x[xo + lane];
        s_x[(lane+32)*PX + w] = g_x[xo + 32 + lane];
        float msk = nm_i ? 1.f : 0.f;
        float4 nd = *(const float4*)&node[(size_t)(b*Ndim + i)*NCdim + lane*4];
        s_x[(64 + lane*4 + 0)*PX + w] = nd.x * msk;
        s_x[(64 + lane*4 + 1)*PX + w] = nd.y * msk;
        s_x[(64 + lane*4 + 2)*PX + w] = nd.z * msk;
        s_x[(64 + lane*4 + 3)*PX + w] = nd.w * msk;
    }
    __syncthreads();

    const int o = tid & 127;
    const int g = tid >> 7;

    {
        float bb = b_nt[o];
        float4 acc = make_float4(bb, bb, bb, bb);
        #pragma unroll 4
        for (int k = 0; k < NIN; k++) {
            float wv = W_nt[k*NCdim + o];
            float4 xi = *(const float4*)&s_x[k*PX + g*4];
            acc.x += wv*xi.x; acc.y += wv*xi.y; acc.z += wv*xi.z; acc.w += wv*xi.w;
        }
        #pragma unroll
        for (int c4 = 0; c4 < 4; c4++) {
            int nn = g*4 + c4;
            float v = (c4 == 0) ? acc.x : (c4 == 1) ? acc.y : (c4 == 2) ? acc.z : acc.w;
            s_hT[o*PX + nn] = (s_bid8[nn] >= 0) ? silu_f(v) : 0.f;
        }
    }
    __syncthreads();

    {
        float bn = b_n1[o], bt = b_no1[o];
        float4 an = make_float4(bn, bn, bn, bn);
        float4 at = make_float4(bt, bt, bt, bt);
        #pragma unroll 4
        for (int k = 0; k < NCdim; k++) {
            float wn = W_n1[k*NCdim + o];
            float wt = W_no1[k*NCdim + o];
            float4 xi = *(const float4*)&s_hT[k*PX + g*4];
            an.x += wn*xi.x; an.y += wn*xi.y; an.z += wn*xi.z; an.w += wn*xi.w;
            at.x += wt*xi.x; at.y += wt*xi.y; at.z += wt*xi.z; at.w += wt*xi.w;
        }
        s_nT[o*PX + g*4+0] = an.x; s_nT[o*PX + g*4+1] = an.y;
        s_nT[o*PX + g*4+2] = an.z; s_nT[o*PX + g*4+3] = an.w;
        s_tT[o*PX + g*4+0] = at.x; s_tT[o*PX + g*4+1] = at.y;
        s_tT[o*PX + g*4+2] = at.z; s_tT[o*PX + g*4+3] = at.w;
    }
    __syncthreads();

    {
        const int oq = tid & 63;
        const int wh = (tid >> 6) & 1;
        float4 aq = make_float4(0.f, 0.f, 0.f, 0.f);
        #pragma unroll 4
        for (int k = 0; k < OCdim; k++) {
            float wq = W_f1[k*OCdim + oq];
            float4 xi = *(const float4*)&s_nT[(wh*OCdim + k)*PX + g*4];
            aq.x += wq*xi.x; aq.y += wq*xi.y; aq.z += wq*xi.z; aq.w += wq*xi.w;
        }
        #pragma unroll
        for (int c4 = 0; c4 < 4; c4++) {
            int nn = g*4 + c4;
            float qv = (c4 == 0) ? aq.x : (c4 == 1) ? aq.y : (c4 == 2) ? aq.z : aq.w;
            size_t base = ((size_t)(b*Ndim + i0 + nn)*OCdim + oq)*4;
            g_pk[base + wh]     = s_nT[(wh*OCdim + oq)*PX + nn];
            g_pk[base + 2 + wh] = qv;
        }
    }

    {
        float tv0 = s_tT[lane*PX + w];
        float tv1 = s_tT[(lane+32)*PX + w];
        float tv2 = s_tT[(lane+64)*PX + w];
        float tv3 = s_tT[(lane+96)*PX + w];
        float s = tv0 + tv1 + tv2 + tv3;
        #pragma unroll
        for (int o2 = 16; o2; o2 >>= 1) s += __shfl_xor_sync(0xffffffffu, s, o2);
        float mean = s * (1.f/NCdim);
        float d0 = tv0-mean, d1 = tv1-mean, d2 = tv2-mean, d3 = tv3-mean;
        float var = d0*d0 + d1*d1 + d2*d2 + d3*d3;
        #pragma unroll
        for (int o2 = 16; o2; o2 >>= 1) var += __shfl_xor_sync(0xffffffffu, var, o2);
        float rstd = rsqrtf(var * (1.f/NCdim) + 1e-5f);
        s_vT[lane*PX + w]      = silu_f(d0*rstd*g_no[lane]    + be_no[lane]);
        s_vT[(lane+32)*PX + w] = silu_f(d1*rstd*g_no[lane+32] + be_no[lane+32]);
        s_vT[(lane+64)*PX + w] = silu_f(d2*rstd*g_no[lane+64] + be_no[lane+64]);
        s_vT[(lane+96)*PX + w] = silu_f(d3*rstd*g_no[lane+96] + be_no[lane+96]);
    }
    __syncthreads();

    if (lane < KNdim) {
        float a = b_no2[lane];
        #pragma unroll 4
        for (int k = 0; k < NCdim; k++)
            a += s_vT[k*PX + w] * W_no2[k*KNdim + lane];
        bool nm_i = (s_bid8[w] >= 0);
        out_node[(size_t)(b*Ndim + i0 + w)*KNdim + lane] = nm_i ? a : 0.f;
    }
}

// ---------------------------------------------------------------------------
// Kernel 2: edge work. silu via tanh.approx.f16x2 in the combine phase:
// MUFU per iter halved; E comes out packed as the eo1 A-fragment.
// ---------------------------------------------------------------------------
#define SM_KEY     0
#define SM_BE1B    2048
#define SM_BF2B    2304
#define SM_BF1     2560
#define SM_NIPK    2816
#define SM_BEO1    4864
#define SM_GEO     4992
#define SM_BEEO    5120
#define SM_BEO2    5248
#define SM_EO2T    5296
#define SM_BE1H    6448
#define SM_BF2H    10544
#define SM_BO1H    18736
#define SM_WARP    22832
#define SM_PERW    1280
#define SM_TOTAL   (SM_WARP + EWARPS*SM_PERW)   // 33072

__global__ __launch_bounds__(256, 2)
void edge_kernel(const float* __restrict__ edge,
                 const int* __restrict__ block_id,
                 const int* __restrict__ vmask,
                 const float* __restrict__ W_e1, const float* __restrict__ b_e1,
                 const float* __restrict__ b_f1,
                 const float* __restrict__ W_f2, const float* __restrict__ b_f2,
                 const float* __restrict__ W_eo1, const float* __restrict__ b_eo1,
                 const float* __restrict__ g_eo, const float* __restrict__ be_eo,
                 const float* __restrict__ W_eo2, const float* __restrict__ b_eo2,
                 float* __restrict__ out_edge)
{
    extern __shared__ char dsm[];
    const int b = blockIdx.x / 257;
    const int m = blockIdx.x % 257;
    const int tid  = threadIdx.x;
    const int w    = tid >> 5;
    const int lane = tid & 31;
    const int grp  = lane >> 2;
    const int q    = lane & 3;

    int i_a, i_b;
    if (m < 255)      { i_a = m + 1; i_b = 511 - m; }
    else if (m == 255){ i_a = 0;     i_b = 0;       }
    else              { i_a = 256;   i_b = 256;     }
    const int npa   = Ndim - i_a;
    const int total = (m < 255) ? 512 : npa;

    int*    s_key  = (int*)(dsm + SM_KEY);
    float*  sbe1b  = (float*)(dsm + SM_BE1B);
    float*  sbf2b  = (float*)(dsm + SM_BF2B);
    float*  sbF1   = (float*)(dsm + SM_BF1);
    float4* s_nipk = (float4*)(dsm + SM_NIPK);
    float*  sbeo1  = (float*)(dsm + SM_BEO1);
    float*  sgeo   = (float*)(dsm + SM_GEO);
    float*  sbeeo  = (float*)(dsm + SM_BEEO);
    float*  sbeo2  = (float*)(dsm + SM_BEO2);
    float*  sw_eo2T = (float*)(dsm + SM_EO2T);
    uint2*  be1h   = (uint2*)(dsm + SM_BE1H);
    uint2*  bf2h   = (uint2*)(dsm + SM_BF2H);
    uint2*  bo1h   = (uint2*)(dsm + SM_BO1H);

    char*  wbase = dsm + SM_WARP + w*SM_PERW;
    float* sv    = (float*)wbase;            // [8][36]
    int*   smi   = (int*)(wbase + 1152);
    int*   smj   = smi + 8;
    float* sem   = (float*)(smi + 16);
    int*   sact  = smi + 24;

    for (int k = tid; k < Ndim; k += 256)
        s_key[k] = block_id[b*Ndim + k]*2 + ((vmask[b*Ndim + k] != 0) ? 1 : 0);
    if (tid < 64)  sbe1b[tid] = b_e1[tid];
    if (tid >= 64 && tid < 128)  sbf2b[tid-64] = b_f2[tid-64];
    if (tid >= 128 && tid < 192) sbF1[tid-128] = b_f1[tid-128];
    if (tid >= 192 && tid < 224) sbeo1[tid-192] = b_eo1[tid-192];
    if (tid >= 224 && tid < 256) sgeo[tid-224] = g_eo[tid-224];
    if (tid < 32)  sbeeo[tid] = be_eo[tid];
    if (tid >= 32 && tid < 40) sbeo2[tid-32] = b_eo2[tid-32];
    if (tid >= 40 && tid < 168) {
        int k = tid - 40;
        int row = k >> 6, ch = k & 63;
        int irow = row ? i_b : i_a;
        s_nipk[k] = *(const float4*)&g_pk[((size_t)(b*Ndim + irow)*OCdim + ch)*4];
    }
    for (int k = tid; k < 8*36; k += 256) {
        int ch = k / 36, kk = k % 36;
        sw_eo2T[k] = (ch < KEdim && kk < ECdim) ? W_eo2[kk*KEdim + ch] : 0.f;
    }
    for (int e = tid; e < 512; e += 256) {
        int lane_ = e & 31, nt = (e >> 5) & 7, ks = e >> 8;
        int q_ = lane_ & 3, g_ = lane_ >> 2;
        int k0 = ks*16 + 2*q_;
        int n  = nt*8 + g_;
        be1h[e] = make_uint2(pack_h2(W_e1[k0*OCdim + n],     W_e1[(k0+1)*OCdim + n]),
                             pack_h2(W_e1[(k0+8)*OCdim + n], W_e1[(k0+9)*OCdim + n]));
    }
    for (int e = tid; e < 1024; e += 256) {
        int lane_ = e & 31, nt = (e >> 5) & 7, ks = e >> 8;
        int q_ = lane_ & 3, g_ = lane_ >> 2;
        int k0 = ks*16 + 2*q_;
        int n  = nt*8 + g_;
        bf2h[e] = make_uint2(pack_h2(W_f2[k0*OCdim + n],     W_f2[(k0+1)*OCdim + n]),
                             pack_h2(W_f2[(k0+8)*OCdim + n], W_f2[(k0+9)*OCdim + n]));
    }
    for (int e = tid; e < 512; e += 256) {
        int lane_ = e & 31, nt = (e >> 5) & 3, ks = e >> 7;
        int q_ = lane_ & 3, g_ = lane_ >> 2;
        int k0 = ks*16 + 2*q_;
        int n  = nt*8 + g_;
        bo1h[e] = make_uint2(pack_h2(W_eo1[k0*32 + n],     W_eo1[(k0+1)*32 + n]),
                             pack_h2(W_eo1[(k0+8)*32 + n], W_eo1[(k0+9)*32 + n]));
    }
    __syncthreads();

    for (int base = w*8; base < total; base += EWARPS*8) {
        if (lane < 8) {
            int p = base + lane;
            int act = (p < total) ? 1 : 0;
            int pc = act ? p : 0;
            bool aA = pc < npa;
            int i2 = aA ? i_a : i_b;
            int j2 = aA ? (i_a + pc) : (i_b + (pc - npa));
            int ki = s_key[i2], kj = s_key[j2];
            int bi_ = ki >> 1, bj_ = kj >> 1;
            bool nm2 = (bi_ >= 0) && (bj_ >= 0);
            bool cij = (bi_ > bj_) || (bi_ == bj_ && !(ki & 1));
            bool cji = (bj_ > bi_) || (bj_ == bi_ && !(kj & 1));
            smi[lane] = i2; smj[lane] = j2;
            sem[lane] = (nm2 && (cij || cji)) ? 1.f : 0.f;
            sact[lane] = act;
        }
        __syncwarp();

        const int   i2  = smi[grp];
        const int   j2  = smj[grp];
        const float emv = sem[grp];
        const bool  isA = (i2 == i_a);
        const __half2 emh = __float2half2_rn(emv);

        uint32_t aEh[8], aEl[8];
        {
            const float* eij = edge + ((size_t)(b*Ndim + i2)*Ndim + j2)*ECdim;
            const float* eji = edge + ((size_t)(b*Ndim + j2)*Ndim + i2)*ECdim;
            #pragma unroll
            for (int ks = 0; ks < 2; ks++) {
                float2 v0 = *(const float2*)(eij + ks*16 + 2*q);
                float2 v1 = *(const float2*)(eji + ks*16 + 2*q);
                float2 v2 = *(const float2*)(eij + ks*16 + 8 + 2*q);
                float2 v3 = *(const float2*)(eji + ks*16 + 8 + 2*q);
                split_h2(v0.x*emv, v0.y*emv, aEh[ks*4+0], aEl[ks*4+0]);
                split_h2(v1.x*emv, v1.y*emv, aEh[ks*4+1], aEl[ks*4+1]);
                split_h2(v2.x*emv, v2.y*emv, aEh[ks*4+2], aEl[ks*4+2]);
                split_h2(v3.x*emv, v3.y*emv, aEh[ks*4+3], aEl[ks*4+3]);
            }
        }

        // e1: 2-pass activation compensation (root of the chain)
        float cE[8][4];
        #pragma unroll
        for (int nt = 0; nt < 8; nt++) {
            float2 bb = *(const float2*)&sbe1b[nt*8 + 2*q];
            cE[nt][0] = bb.x; cE[nt][1] = bb.y; cE[nt][2] = bb.x; cE[nt][3] = bb.y;
        }
        #pragma unroll
        for (int ks = 0; ks < 2; ks++) {
            #pragma unroll
            for (int nt = 0; nt < 8; nt++) {
                uint2 Bh = be1h[(ks*8 + nt)*32 + lane];
                mma16816(cE[nt][0], cE[nt][1], cE[nt][2], cE[nt][3],
                         aEh[ks*4+0], aEh[ks*4+1], aEh[ks*4+2], aEh[ks*4+3], Bh.x, Bh.y);
                mma16816(cE[nt][0], cE[nt][1], cE[nt][2], cE[nt][3],
                         aEl[ks*4+0], aEl[ks*4+1], aEl[ks*4+2], aEl[ks*4+3], Bh.x, Bh.y);
            }
        }

        uint32_t e1h[16];
        #pragma unroll
        for (int ks = 0; ks < 4; ks++) {
            e1h[ks*4+0] = pack_h2(cE[2*ks][0],   cE[2*ks][1]);
            e1h[ks*4+1] = pack_h2(cE[2*ks][2],   cE[2*ks][3]);
            e1h[ks*4+2] = pack_h2(cE[2*ks+1][0], cE[2*ks+1][1]);
            e1h[ks*4+3] = pack_h2(cE[2*ks+1][2], cE[2*ks+1][3]);
        }

        float cF[8][4];
        #pragma unroll
        for (int nt = 0; nt < 8; nt++) {
            float2 bb = *(const float2*)&sbf2b[nt*8 + 2*q];
            cF[nt][0] = bb.x; cF[nt][1] = bb.y; cF[nt][2] = bb.x; cF[nt][3] = bb.y;
        }
        #pragma unroll
        for (int ks = 0; ks < 4; ks++) {
            #pragma unroll
            for (int nt = 0; nt < 8; nt++) {
                uint2 Bh = bf2h[(ks*8 + nt)*32 + lane];
                mma16816(cF[nt][0], cF[nt][1], cF[nt][2], cF[nt][3],
                         e1h[ks*4+0], e1h[ks*4+1], e1h[ks*4+2], e1h[ks*4+3], Bh.x, Bh.y);
            }
        }

        // combine -> masked E directly packed as eo1 A-fragments (h2 silu)
        uint32_t aUh[16];
        {
            const float4* gpk = (const float4*)g_pk;
            const size_t jo = (size_t)(b*Ndim + j2)*OCdim;
            const int    ib = isA ? 0 : 64;
            #pragma unroll
            for (int nt = 0; nt < 8; nt++) {
                const int ch0 = nt*8 + 2*q;
                const int kss = nt >> 1, sub = nt & 1;
                const float* e1src = cE[2*kss + sub];
                float4 pj0 = gpk[jo + ch0];
                float4 pj1 = gpk[jo + ch0 + 1];
                float4 pi0 = s_nipk[ib + ch0];
                float4 pi1 = s_nipk[ib + ch0 + 1];
                float2 bf  = *(const float2*)&sbF1[ch0];
                __half2 Qij = silu_h2(pj0.z + pi0.w + bf.x, pj1.z + pi1.w + bf.y);
                __half2 Qji = silu_h2(pi0.z + pj0.w + bf.x, pi1.z + pj1.w + bf.y);
                __half2 Fij = silu_h2(cF[nt][0], cF[nt][1]);
                __half2 Fji = silu_h2(cF[nt][2], cF[nt][3]);
                float2 qfij = __half22float2(__hmul2(Qij, Fij));
                float2 qfji = __half22float2(__hmul2(Qji, Fji));
                __half2 Eij = silu_h2(pj0.x + pi0.y + e1src[0] + qfij.x,
                                      pj1.x + pi1.y + e1src[1] + qfij.y);
                __half2 Eji = silu_h2(pi0.x + pj0.y + e1src[2] + qfji.x,
                                      pi1.x + pj1.y + e1src[3] + qfji.y);
                Eij = __hmul2(Eij, emh);
                Eji = __hmul2(Eji, emh);
                const int bse = kss*4 + sub*2;
                aUh[bse]   = *(uint32_t*)&Eij;
                aUh[bse+1] = *(uint32_t*)&Eji;
            }
        }

        // eo1 single-pass
        float cU[4][4];
        #pragma unroll
        for (int nt = 0; nt < 4; nt++)
            cU[nt][0] = cU[nt][1] = cU[nt][2] = cU[nt][3] = 0.f;
        #pragma unroll
        for (int ks = 0; ks < 4; ks++) {
            #pragma unroll
            for (int nt = 0; nt < 4; nt++) {
                uint2 Bh = bo1h[(ks*4 + nt)*32 + lane];
                mma16816(cU[nt][0], cU[nt][1], cU[nt][2], cU[nt][3],
                         aUh[ks*4+0], aUh[ks*4+1], aUh[ks*4+2], aUh[ks*4+3], Bh.x, Bh.y);
            }
        }

        float u0[4], u1[4];
        float s = 0.f;
        #pragma unroll
        for (int nt = 0; nt < 4; nt++) {
            float2 bb = *(const float2*)&sbeo1[nt*8 + 2*q];
            u0[nt] = cU[nt][0] + cU[nt][2] + bb.x;
            u1[nt] = cU[nt][1] + cU[nt][3] + bb.y;
            s += u0[nt] + u1[nt];
        }
        s += __shfl_xor_sync(0xffffffffu, s, 1);
        s += __shfl_xor_sync(0xffffffffu, s, 2);
        const float mean = s * (1.f/32.f);
        float var = 0.f;
        #pragma unroll
        for (int nt = 0; nt < 4; nt++) {
            float d0 = u0[nt] - mean, d1 = u1[nt] - mean;
            var += d0*d0 + d1*d1;
        }
        var += __shfl_xor_sync(0xffffffffu, var, 1);
        var += __shfl_xor_sync(0xffffffffu, var, 2);
        const float rstd = rsqrtf(var * (1.f/32.f) + 1e-5f);
        #pragma unroll
        for (int nt = 0; nt < 4; nt++) {
            const int ch0 = nt*8 + 2*q;
            float2 ge = *(const float2*)&sgeo[ch0];
            float2 be = *(const float2*)&sbeeo[ch0];
            float v0 = silu_t((u0[nt] - mean)*rstd*ge.x + be.x);
            float v1 = silu_t((u1[nt] - mean)*rstd*ge.y + be.y);
            *(float2*)&sv[grp*36 + ch0] = make_float2(v0, v1);
        }
        __syncwarp();

        #pragma unroll
        for (int h = 0; h < 2; h++) {
            const int pr  = h*4 + (lane >> 3);
            const int ch2 = lane & 7;
            float t = 0.f;
            #pragma unroll
            for (int k4 = 0; k4 < 8; k4++) {
                float4 vv = *(const float4*)&sv[pr*36 + k4*4];
                float4 w4 = *(const float4*)&sw_eo2T[ch2*36 + k4*4];
                t += vv.x*w4.x + vv.y*w4.y + vv.z*w4.z + vv.w*w4.w;
            }
            if (ch2 < KEdim && sact[pr]) {
                const int io = smi[pr], jo2 = smj[pr];
                float outv = (t + sbeo2[ch2]) * sem[pr];
                out_edge[((size_t)(b*Ndim + io)*Ndim + jo2)*KEdim + ch2] = outv;
                out_edge[((size_t)(b*Ndim + jo2)*Ndim + io)*KEdim + ch2] = outv;
            }
        }
        __syncwarp();
    }
}

// ---------------------------------------------------------------------------
extern "C" void kernel_launch(void* const* d_in, const int* in_sizes, int n_in,
                              void* d_out, int out_size)
{
    const float* node      = (const float*)d_in[0];
    const float* edge      = (const float*)d_in[1];
    const int*   block_id  = (const int*)d_in[2];
    const int*   vmask     = (const int*)d_in[3];
    const float* W_nt  = (const float*)d_in[4];
    const float* b_nt  = (const float*)d_in[5];
    const float* W_n1  = (const float*)d_in[6];
    const float* b_n1  = (const float*)d_in[7];
    const float* W_e1  = (const float*)d_in[8];
    const float* b_e1  = (const float*)d_in[9];
    const float* W_f1  = (const float*)d_in[10];
    const float* b_f1  = (const float*)d_in[11];
    const float* W_f2  = (const float*)d_in[12];
    const float* b_f2  = (const float*)d_in[13];
    const float* W_no1 = (const float*)d_in[14];
    const float* b_no1 = (const float*)d_in[15];
    const float* g_no  = (const float*)d_in[16];
    const float* be_no = (const float*)d_in[17];
    const float* W_no2 = (const float*)d_in[18];
    const float* b_no2 = (const float*)d_in[19];
    const float* W_eo1 = (const float*)d_in[20];
    const float* b_eo1 = (const float*)d_in[21];
    const float* g_eo  = (const float*)d_in[22];
    const float* be_eo = (const float*)d_in[23];
    const float* W_eo2 = (const float*)d_in[24];
    const float* b_eo2 = (const float*)d_in[25];

    float* out_node = (float*)d_out;                       // (B,N,KN)
    float* out_edge = (float*)d_out + Bdim*Ndim*KNdim;     // (B,N,N,KE)

    static int smem_set = 0;
    if (!smem_set) {
        cudaFuncSetAttribute(edge_kernel, cudaFuncAttributeMaxDynamicSharedMemorySize, SM_TOTAL);
        smem_set = 1;
    }

    reduce_kernel<<<Bdim*Ndim, 256>>>(edge, block_id, vmask);

    node_kernel<<<Bdim*64, 256>>>(node, block_id,
                                  W_nt, b_nt, W_n1, b_n1, W_f1,
                                  W_no1, b_no1, g_no, be_no, W_no2, b_no2,
                                  out_node);

    edge_kernel<<<Bdim*257, 256, SM_TOTAL>>>(edge, block_id, vmask,
                                   W_e1, b_e1, b_f1, W_f2, b_f2,
                                   W_eo1, b_eo1, g_eo, be_eo, W_eo2, b_eo2,
                                   out_edge);
}